// round 5
// baseline (speedup 1.0000x reference)
#include <cuda_runtime.h>
#include <cuda_bf16.h>

#define VOCAB   50257
#define DIM     128
#define BATCH   32
#define M_SLOTS 512
#define S_TOK   6
#define T_TREE  128
#define L_TOK   64
#define SLOTS   (M_SLOTS + T_TREE)   // 640

#define SPLITS   40
#define SLOTS_PB (SLOTS / SPLITS)    // 16
#define REC      132                 // m, s, pad, pad, o[128]
#define GBLK     (BATCH * SLOTS / 8) // 2560 gather blocks per table
#define HOPBLK   (BATCH * SPLITS)    // 1280 hop blocks

// g_M[t] holds table (t+1): tables 1..3. 31.5 MB
__device__ float g_M[(size_t)3 * BATCH * SLOTS * DIM];
__device__ __align__(16) float g_part[(size_t)2 * BATCH * SPLITS * REC];
__device__ __align__(16) float g_u[2 * BATCH * DIM];   // [0]=u1, [1]=u2

__device__ __forceinline__ float warp_max(float v) {
    #pragma unroll
    for (int o = 16; o; o >>= 1) v = fmaxf(v, __shfl_xor_sync(0xffffffffu, v, o));
    return v;
}
__device__ __forceinline__ float warp_sum(float v) {
    #pragma unroll
    for (int o = 16; o; o >>= 1) v += __shfl_xor_sync(0xffffffffu, v, o);
    return v;
}

// ---------------------------------------------------------------------------
// Gather one (table, block) of 8 slots. t in 0..2 selects table t+1.
// ---------------------------------------------------------------------------
__device__ __forceinline__ void gather_body(
    int t, int blk,
    const float* __restrict__ C,
    const int*   __restrict__ story,
    const int*   __restrict__ kb)
{
    const int lane = threadIdx.x & 31;
    const int rem  = blk * 8 + (threadIdx.x >> 5);   // (b, slot) index
    const int b    = rem / SLOTS;
    const int slot = rem % SLOTS;

    const float4* __restrict__ Ct =
        reinterpret_cast<const float4*>(C + (size_t)(t + 1) * VOCAB * DIM);

    float4 acc = make_float4(0.f, 0.f, 0.f, 0.f);

    if (slot < M_SLOTS) {
        const int* toks = story + ((size_t)b * M_SLOTS + slot) * S_TOK;
        int tk[S_TOK];
        #pragma unroll
        for (int j = 0; j < S_TOK; ++j) tk[j] = toks[j];
        #pragma unroll
        for (int j = 0; j < S_TOK; ++j) {
            float4 v = Ct[(size_t)tk[j] * (DIM / 4) + lane];
            acc.x += v.x; acc.y += v.y; acc.z += v.z; acc.w += v.w;
        }
    } else {
        const int* toks = kb + ((size_t)b * T_TREE + (slot - M_SLOTS)) * L_TOK;
        float4 a0 = make_float4(0.f, 0.f, 0.f, 0.f);
        float4 a1 = a0, a2 = a0, a3 = a0;
        #pragma unroll 4
        for (int j = 0; j < L_TOK; j += 4) {
            int t0 = toks[j + 0], t1 = toks[j + 1];
            int t2 = toks[j + 2], t3 = toks[j + 3];
            float4 v0 = Ct[(size_t)t0 * (DIM / 4) + lane];
            float4 v1 = Ct[(size_t)t1 * (DIM / 4) + lane];
            float4 v2 = Ct[(size_t)t2 * (DIM / 4) + lane];
            float4 v3 = Ct[(size_t)t3 * (DIM / 4) + lane];
            a0.x += v0.x; a0.y += v0.y; a0.z += v0.z; a0.w += v0.w;
            a1.x += v1.x; a1.y += v1.y; a1.z += v1.z; a1.w += v1.w;
            a2.x += v2.x; a2.y += v2.y; a2.z += v2.z; a2.w += v2.w;
            a3.x += v3.x; a3.y += v3.y; a3.z += v3.z; a3.w += v3.w;
        }
        acc.x = (a0.x + a1.x) + (a2.x + a3.x);
        acc.y = (a0.y + a1.y) + (a2.y + a3.y);
        acc.z = (a0.z + a1.z) + (a2.z + a3.z);
        acc.w = (a0.w + a1.w) + (a2.w + a3.w);
    }

    float4* out = reinterpret_cast<float4*>(g_M) +
                  ((size_t)t * BATCH * SLOTS + rem) * (DIM / 4);
    out[lane] = acc;
}

// ---------------------------------------------------------------------------
// u1[b] = mean over 640 slots of table-1 memory (hop 0 softmax is uniform).
// 256-thread block: d = tid&127, half = tid>>7 sums 320 slots.
// ---------------------------------------------------------------------------
__device__ __forceinline__ void u1_body(int b)
{
    const int d    = threadIdx.x & 127;
    const int half = threadIdx.x >> 7;
    const float* __restrict__ base = g_M + (size_t)b * SLOTS * DIM;  // table1

    float acc = 0.f;
    #pragma unroll 4
    for (int s = half * 320; s < (half + 1) * 320; ++s)
        acc += base[(size_t)s * DIM + d];

    __shared__ float sm[256];
    sm[threadIdx.x] = acc;
    __syncthreads();
    if (half == 0)
        g_u[b * DIM + d] = (sm[d] + sm[128 + d]) * (1.0f / SLOTS);
}

// ---------------------------------------------------------------------------
// One hop split-block: 16 slots, flash-style partial (m, s, o[128]).
// ---------------------------------------------------------------------------
__device__ __forceinline__ void hop_body(int kidx, int vidx, int uidx,
                                         int pidx, int hb)
{
    const int b     = hb / SPLITS;
    const int split = hb % SPLITS;
    const int w     = threadIdx.x >> 5;
    const int lane  = threadIdx.x & 31;

    __shared__ float  s_score[SLOTS_PB];
    __shared__ float4 s_part[8][32];
    __shared__ float  s_ms[2];

    const float4 u4 =
        reinterpret_cast<const float4*>(g_u + (uidx * BATCH + b) * DIM)[lane];

    const float* __restrict__ Mk =
        g_M + ((size_t)(kidx * BATCH + b) * SLOTS + split * SLOTS_PB) * DIM;
    const float* __restrict__ Mv =
        g_M + ((size_t)(vidx * BATCH + b) * SLOTS + split * SLOTS_PB) * DIM;

    #pragma unroll
    for (int k = 0; k < SLOTS_PB / 8; ++k) {
        const int ls = w + k * 8;
        const float4 v = reinterpret_cast<const float4*>(Mk + (size_t)ls * DIM)[lane];
        float p = v.x * u4.x + v.y * u4.y + v.z * u4.z + v.w * u4.w;
        p = warp_sum(p);
        if (lane == 0) s_score[ls] = p;
    }
    __syncthreads();

    if (w == 0) {
        float sc = (lane < SLOTS_PB) ? s_score[lane] : -1e30f;
        float m  = warp_max(sc);
        float e  = (lane < SLOTS_PB) ? __expf(sc - m) : 0.f;
        float s  = warp_sum(e);
        if (lane < SLOTS_PB) s_score[lane] = e;
        if (lane == 0) { s_ms[0] = m; s_ms[1] = s; }
    }
    __syncthreads();

    float4 o4 = make_float4(0.f, 0.f, 0.f, 0.f);
    #pragma unroll
    for (int k = 0; k < SLOTS_PB / 8; ++k) {
        const int ls = w + k * 8;
        const float  p = s_score[ls];
        const float4 v = reinterpret_cast<const float4*>(Mv + (size_t)ls * DIM)[lane];
        o4.x += p * v.x; o4.y += p * v.y; o4.z += p * v.z; o4.w += p * v.w;
    }
    s_part[w][lane] = o4;
    __syncthreads();

    if (w == 0) {
        float4 r = make_float4(0.f, 0.f, 0.f, 0.f);
        #pragma unroll
        for (int i = 0; i < 8; ++i) {
            float4 p = s_part[i][lane];
            r.x += p.x; r.y += p.y; r.z += p.z; r.w += p.w;
        }
        float* rec = g_part + ((size_t)(pidx * BATCH + b) * SPLITS + split) * REC;
        reinterpret_cast<float4*>(rec + 4)[lane] = r;
        if (lane == 0) { rec[0] = s_ms[0]; rec[1] = s_ms[1]; }
    }
}

// ---------------------------------------------------------------------------
// K1: gather table 1 (pure).
// ---------------------------------------------------------------------------
__global__ void __launch_bounds__(256) k1_gather_t1(
    const float* __restrict__ C, const int* __restrict__ story,
    const int* __restrict__ kb)
{
    gather_body(0, blockIdx.x, C, story, kb);
}

// K2: blocks 0..31 compute u1 (needs table1); rest gather table 2.
__global__ void __launch_bounds__(256) k2_u1_gather_t2(
    const float* __restrict__ C, const int* __restrict__ story,
    const int* __restrict__ kb)
{
    if (blockIdx.x < BATCH) u1_body(blockIdx.x);
    else                    gather_body(1, blockIdx.x - BATCH, C, story, kb);
}

// K3: hop-1 blocks interleaved 1:2 with table-3 gather blocks.
__global__ void __launch_bounds__(256) k3_hop1_gather_t3(
    const float* __restrict__ C, const int* __restrict__ story,
    const int* __restrict__ kb)
{
    const int q = blockIdx.x / 3;
    const int r = blockIdx.x % 3;
    if (r == 0) hop_body(0, 1, 0, 0, q);                 // M1 key, M2 val, u1
    else        gather_body(2, q * 2 + (r - 1), C, story, kb);
}

// K5: hop 2 (pure).
__global__ void __launch_bounds__(256) k5_hop2()
{
    hop_body(1, 2, 1, 1, blockIdx.x);                    // M2 key, M3 val, u2
}

// ---------------------------------------------------------------------------
// Combine split partials: dst[b] = u[u_src][b] + o/s. Block per b, 8 warps.
// ---------------------------------------------------------------------------
__global__ void __launch_bounds__(256) combine_kernel(int pidx, int u_src,
                                                      float* __restrict__ dst)
{
    const int b    = blockIdx.x;
    const int tid  = threadIdx.x;
    const int w    = tid >> 5;
    const int lane = tid & 31;

    const float* __restrict__ base =
        g_part + ((size_t)(pidx * BATCH + b)) * SPLITS * REC;

    __shared__ float  s_m[8], s_s[8];
    __shared__ float4 s_o[8][32];

    // global max over 40 record maxima
    float mi = (tid < SPLITS) ? base[(size_t)tid * REC] : -1e30f;
    mi = warp_max(mi);
    if (lane == 0) s_m[w] = mi;
    __syncthreads();
    float m = s_m[0];
    #pragma unroll
    for (int i = 1; i < 8; ++i) m = fmaxf(m, s_m[i]);

    // warp w accumulates records w, w+8, ..., w+32
    float  s_acc = 0.f;
    float4 o4 = make_float4(0.f, 0.f, 0.f, 0.f);
    #pragma unroll
    for (int k = 0; k < SPLITS / 8; ++k) {
        const float* rec = base + (size_t)(w + 8 * k) * REC;
        float e = __expf(rec[0] - m);
        s_acc += rec[1] * e;
        float4 oi = reinterpret_cast<const float4*>(rec + 4)[lane];
        o4.x += e * oi.x; o4.y += e * oi.y; o4.z += e * oi.z; o4.w += e * oi.w;
    }
    s_o[w][lane] = o4;
    if (lane == 0) s_s[w] = s_acc;
    __syncthreads();

    if (w == 0) {
        float stot = 0.f;
        #pragma unroll
        for (int i = 0; i < 8; ++i) stot += s_s[i];
        float4 r = make_float4(0.f, 0.f, 0.f, 0.f);
        #pragma unroll
        for (int i = 0; i < 8; ++i) {
            float4 p = s_o[i][lane];
            r.x += p.x; r.y += p.y; r.z += p.z; r.w += p.w;
        }
        const float inv = 1.0f / stot;
        const float4 u4 =
            reinterpret_cast<const float4*>(g_u + (u_src * BATCH + b) * DIM)[lane];
        float4 res;
        res.x = u4.x + r.x * inv;
        res.y = u4.y + r.y * inv;
        res.z = u4.z + r.z * inv;
        res.w = u4.w + r.w * inv;
        reinterpret_cast<float4*>(dst + b * DIM)[lane] = res;
    }
}

// ---------------------------------------------------------------------------
extern "C" void kernel_launch(void* const* d_in, const int* in_sizes, int n_in,
                              void* d_out, int out_size)
{
    const float* C     = (const float*)d_in[0];  // [4, 50257, 128]
    const int*   story = (const int*)  d_in[1];  // [32, 512, 6]
    const int*   kb    = (const int*)  d_in[2];  // [32, 128, 64]
    float*       out   = (float*)d_out;          // [32, 128]

    float* u2;
    cudaGetSymbolAddress((void**)&u2, g_u);
    u2 += BATCH * DIM;

    k1_gather_t1<<<GBLK, 256>>>(C, story, kb);                 // 2560
    k2_u1_gather_t2<<<GBLK + BATCH, 256>>>(C, story, kb);      // 2592
    k3_hop1_gather_t3<<<HOPBLK + GBLK, 256>>>(C, story, kb);   // 3840
    combine_kernel<<<BATCH, 256>>>(0, 0, u2);                  // u2 = u1 + o1
    k5_hop2<<<HOPBLK, 256>>>();                                // 1280
    combine_kernel<<<BATCH, 256>>>(1, 1, out);                 // out = u2 + o2
}

// round 6
// speedup vs baseline: 1.3009x; 1.3009x over previous
#include <cuda_runtime.h>
#include <cuda_bf16.h>

#define VOCAB   50257
#define DIM     128
#define BATCH   32
#define M_SLOTS 512
#define S_TOK   6
#define T_TREE  128
#define L_TOK   64
#define SLOTS   (M_SLOTS + T_TREE)   // 640

#define SPLITS   80
#define SLOTS_PB (SLOTS / SPLITS)    // 8 slots per hop block
#define REC      132                 // m, s, pad, pad, o[128]
#define GBLK_PER_TAB (BATCH * SLOTS / 8)   // 2560
#define U1_BLOCKS    (SLOTS / 8)           // 80 table-1 blocks per batch

// g_M[t] holds table (t+1): tables 1..3. 31.5 MB
__device__ float g_M[(size_t)3 * BATCH * SLOTS * DIM];
__device__ __align__(16) float g_part[(size_t)2 * BATCH * SPLITS * REC];
__device__ __align__(16) float g_u[2 * BATCH * DIM];   // [0]=u1, [1]=u2
__device__ int g_cnt[3 * BATCH];   // [0..31] hop1, [32..63] hop2, [64..95] u1

__device__ __forceinline__ float warp_max(float v) {
    #pragma unroll
    for (int o = 16; o; o >>= 1) v = fmaxf(v, __shfl_xor_sync(0xffffffffu, v, o));
    return v;
}
__device__ __forceinline__ float warp_sum(float v) {
    #pragma unroll
    for (int o = 16; o; o >>= 1) v += __shfl_xor_sync(0xffffffffu, v, o);
    return v;
}

// ---------------------------------------------------------------------------
// Phase 1: gather-sum tables 1..3, one warp per (t,b,slot).
// Last table-1 block per batch additionally computes u1[b] (uniform hop 0).
// ---------------------------------------------------------------------------
__global__ void __launch_bounds__(256) gather_kernel(
    const float* __restrict__ C,
    const int*   __restrict__ story,
    const int*   __restrict__ kb)
{
    const int lane = threadIdx.x & 31;
    const int wg   = blockIdx.x * 8 + (threadIdx.x >> 5);
    const int t    = wg / (BATCH * SLOTS);           // 0..2 -> table t+1
    const int rem  = wg % (BATCH * SLOTS);
    const int b    = rem / SLOTS;
    const int slot = rem % SLOTS;

    const float4* __restrict__ Ct =
        reinterpret_cast<const float4*>(C + (size_t)(t + 1) * VOCAB * DIM);

    float4 acc = make_float4(0.f, 0.f, 0.f, 0.f);

    if (slot < M_SLOTS) {
        const int* toks = story + ((size_t)b * M_SLOTS + slot) * S_TOK;
        int tk[S_TOK];
        #pragma unroll
        for (int j = 0; j < S_TOK; ++j) tk[j] = toks[j];
        #pragma unroll
        for (int j = 0; j < S_TOK; ++j) {
            float4 v = Ct[(size_t)tk[j] * (DIM / 4) + lane];
            acc.x += v.x; acc.y += v.y; acc.z += v.z; acc.w += v.w;
        }
    } else {
        const int* toks = kb + ((size_t)b * T_TREE + (slot - M_SLOTS)) * L_TOK;
        float4 a0 = make_float4(0.f, 0.f, 0.f, 0.f);
        float4 a1 = a0, a2 = a0, a3 = a0;
        #pragma unroll 4
        for (int j = 0; j < L_TOK; j += 4) {
            int t0 = toks[j + 0], t1 = toks[j + 1];
            int t2 = toks[j + 2], t3 = toks[j + 3];
            float4 v0 = Ct[(size_t)t0 * (DIM / 4) + lane];
            float4 v1 = Ct[(size_t)t1 * (DIM / 4) + lane];
            float4 v2 = Ct[(size_t)t2 * (DIM / 4) + lane];
            float4 v3 = Ct[(size_t)t3 * (DIM / 4) + lane];
            a0.x += v0.x; a0.y += v0.y; a0.z += v0.z; a0.w += v0.w;
            a1.x += v1.x; a1.y += v1.y; a1.z += v1.z; a1.w += v1.w;
            a2.x += v2.x; a2.y += v2.y; a2.z += v2.z; a2.w += v2.w;
            a3.x += v3.x; a3.y += v3.y; a3.z += v3.z; a3.w += v3.w;
        }
        acc.x = (a0.x + a1.x) + (a2.x + a3.x);
        acc.y = (a0.y + a1.y) + (a2.y + a3.y);
        acc.z = (a0.z + a1.z) + (a2.z + a3.z);
        acc.w = (a0.w + a1.w) + (a2.w + a3.w);
    }

    float4* out = reinterpret_cast<float4*>(g_M) + (size_t)wg * (DIM / 4);
    out[lane] = acc;

    // ---- last table-1 block for this batch computes u1[b] ----
    if (t == 0) {
        __threadfence();
        __syncthreads();
        __shared__ int s_old;
        if (threadIdx.x == 0)
            s_old = atomicAdd(&g_cnt[2 * BATCH + b], 1);
        __syncthreads();
        if (s_old == U1_BLOCKS - 1) {
            const int d    = threadIdx.x & 127;
            const int half = threadIdx.x >> 7;
            const float* __restrict__ base = g_M + (size_t)b * SLOTS * DIM;
            float acc1 = 0.f;
            #pragma unroll 8
            for (int s = half * 320; s < (half + 1) * 320; ++s)
                acc1 += base[(size_t)s * DIM + d];
            __shared__ float sm[256];
            sm[threadIdx.x] = acc1;
            __syncthreads();
            if (half == 0)
                g_u[b * DIM + d] = (sm[d] + sm[128 + d]) * (1.0f / SLOTS);
            if (threadIdx.x == 0) g_cnt[2 * BATCH + b] = 0;   // reset for replay
        }
    }
}

// ---------------------------------------------------------------------------
// One hop: block = (b, split) handles 8 slots, writes flash partial; the
// last split-block for each b combines all 80 partials into dst[b].
// ---------------------------------------------------------------------------
__global__ void __launch_bounds__(256) hop_kernel(int kidx, int vidx,
                                                  int uidx, int pidx,
                                                  float* __restrict__ dst)
{
    const int b     = blockIdx.x / SPLITS;
    const int split = blockIdx.x % SPLITS;
    const int tid   = threadIdx.x;
    const int w     = tid >> 5;
    const int lane  = tid & 31;

    __shared__ float  s_score[SLOTS_PB];
    __shared__ float4 s_part[8][32];
    __shared__ float  s_ms[2];

    const float4 u4 =
        reinterpret_cast<const float4*>(g_u + (uidx * BATCH + b) * DIM)[lane];

    const float* __restrict__ Mk =
        g_M + ((size_t)(kidx * BATCH + b) * SLOTS + split * SLOTS_PB) * DIM;
    const float* __restrict__ Mv =
        g_M + ((size_t)(vidx * BATCH + b) * SLOTS + split * SLOTS_PB) * DIM;

    // score: warp w handles local slot w
    {
        const float4 v = reinterpret_cast<const float4*>(Mk + (size_t)w * DIM)[lane];
        float p = v.x * u4.x + v.y * u4.y + v.z * u4.z + v.w * u4.w;
        p = warp_sum(p);
        if (lane == 0) s_score[w] = p;
    }
    __syncthreads();

    // local softmax over 8 scores
    if (w == 0) {
        float sc = (lane < SLOTS_PB) ? s_score[lane] : -1e30f;
        float m  = warp_max(sc);
        float e  = (lane < SLOTS_PB) ? __expf(sc - m) : 0.f;
        float s  = warp_sum(e);
        if (lane < SLOTS_PB) s_score[lane] = e;
        if (lane == 0) { s_ms[0] = m; s_ms[1] = s; }
    }
    __syncthreads();

    // weighted value partial
    {
        const float  p = s_score[w];
        const float4 v = reinterpret_cast<const float4*>(Mv + (size_t)w * DIM)[lane];
        s_part[w][lane] = make_float4(p * v.x, p * v.y, p * v.z, p * v.w);
    }
    __syncthreads();

    if (w == 0) {
        float4 r = make_float4(0.f, 0.f, 0.f, 0.f);
        #pragma unroll
        for (int i = 0; i < 8; ++i) {
            float4 p = s_part[i][lane];
            r.x += p.x; r.y += p.y; r.z += p.z; r.w += p.w;
        }
        float* rec = g_part + ((size_t)(pidx * BATCH + b) * SPLITS + split) * REC;
        reinterpret_cast<float4*>(rec + 4)[lane] = r;
        if (lane == 0) { rec[0] = s_ms[0]; rec[1] = s_ms[1]; }
    }

    // ---- last-block combine ----
    __threadfence();
    __syncthreads();
    __shared__ int s_old;
    if (tid == 0)
        s_old = atomicAdd(&g_cnt[pidx * BATCH + b], 1);
    __syncthreads();
    if (s_old != SPLITS - 1) return;

    const float* __restrict__ base =
        g_part + ((size_t)(pidx * BATCH + b)) * SPLITS * REC;

    __shared__ float  c_m[8], c_s[8];
    __shared__ float4 c_o[8][32];

    float mi = (tid < SPLITS) ? __ldcg(base + (size_t)tid * REC) : -1e30f;
    mi = warp_max(mi);
    if (lane == 0) c_m[w] = mi;
    __syncthreads();
    float m = c_m[0];
    #pragma unroll
    for (int i = 1; i < 8; ++i) m = fmaxf(m, c_m[i]);

    // warp w accumulates records w, w+8, ..., w+72
    float  s_acc = 0.f;
    float4 o4 = make_float4(0.f, 0.f, 0.f, 0.f);
    #pragma unroll
    for (int k = 0; k < SPLITS / 8; ++k) {
        const float* rec = base + (size_t)(w + 8 * k) * REC;
        float e = __expf(__ldcg(rec) - m);
        s_acc += __ldcg(rec + 1) * e;
        float4 oi = __ldcg(reinterpret_cast<const float4*>(rec + 4) + lane);
        o4.x += e * oi.x; o4.y += e * oi.y; o4.z += e * oi.z; o4.w += e * oi.w;
    }
    c_o[w][lane] = o4;
    if (lane == 0) c_s[w] = s_acc;
    __syncthreads();

    if (w == 0) {
        float stot = 0.f;
        #pragma unroll
        for (int i = 0; i < 8; ++i) stot += c_s[i];
        float4 r = make_float4(0.f, 0.f, 0.f, 0.f);
        #pragma unroll
        for (int i = 0; i < 8; ++i) {
            float4 p = c_o[i][lane];
            r.x += p.x; r.y += p.y; r.z += p.z; r.w += p.w;
        }
        const float inv = 1.0f / stot;
        float4 res;
        res.x = u4.x + r.x * inv;
        res.y = u4.y + r.y * inv;
        res.z = u4.z + r.z * inv;
        res.w = u4.w + r.w * inv;
        reinterpret_cast<float4*>(dst + b * DIM)[lane] = res;
    }
    if (tid == 0) g_cnt[pidx * BATCH + b] = 0;   // reset for graph replay
}

// ---------------------------------------------------------------------------
extern "C" void kernel_launch(void* const* d_in, const int* in_sizes, int n_in,
                              void* d_out, int out_size)
{
    const float* C     = (const float*)d_in[0];  // [4, 50257, 128]
    const int*   story = (const int*)  d_in[1];  // [32, 512, 6]
    const int*   kb    = (const int*)  d_in[2];  // [32, 128, 64]
    float*       out   = (float*)d_out;          // [32, 128]

    float* u2;
    cudaGetSymbolAddress((void**)&u2, g_u);
    u2 += BATCH * DIM;

    gather_kernel<<<3 * GBLK_PER_TAB, 256>>>(C, story, kb);     // 7680, + u1
    hop_kernel<<<BATCH * SPLITS, 256>>>(0, 1, 0, 0, u2);        // hop1 -> u2
    hop_kernel<<<BATCH * SPLITS, 256>>>(1, 2, 1, 1, out);       // hop2 -> out
}

// round 7
// speedup vs baseline: 1.3431x; 1.0324x over previous
#include <cuda_runtime.h>
#include <cuda_fp16.h>

#define VOCAB   50257
#define DIM     128
#define BATCH   32
#define M_SLOTS 512
#define S_TOK   6
#define T_TREE  128
#define L_TOK   64
#define SLOTS   (M_SLOTS + T_TREE)   // 640

#define SPLITS   40
#define SLOTS_PB (SLOTS / SPLITS)    // 16 slots per hop block
#define REC      132                 // m, s, pad, pad, o[128]
#define GBLK_PER_TAB (BATCH * SLOTS / 8)   // 2560
#define U1_BLOCKS    (SLOTS / 8)           // 80 table-1 blocks per batch
#define CN  ((size_t)3 * VOCAB * DIM)      // floats in tables 1..3

// fp16 copy of tables 1..3 (38.6 MB), fp16 slot memories (15.7 MB)
__device__ __align__(16) __half g_Ch[CN];
__device__ __align__(16) __half g_Mh[(size_t)3 * BATCH * SLOTS * DIM];
__device__ __align__(16) float  g_part[(size_t)2 * BATCH * SPLITS * REC];
__device__ __align__(16) float  g_u[2 * BATCH * DIM];   // [0]=u1, [1]=u2
__device__ int g_cnt[3 * BATCH];   // [0..31] hop1, [32..63] hop2, [64..95] u1

__device__ __forceinline__ float warp_max(float v) {
    #pragma unroll
    for (int o = 16; o; o >>= 1) v = fmaxf(v, __shfl_xor_sync(0xffffffffu, v, o));
    return v;
}
__device__ __forceinline__ float warp_sum(float v) {
    #pragma unroll
    for (int o = 16; o; o >>= 1) v += __shfl_xor_sync(0xffffffffu, v, o);
    return v;
}
__device__ __forceinline__ void acc_u2(float4& a, uint2 v) {
    float2 f0 = __half22float2(*reinterpret_cast<__half2*>(&v.x));
    float2 f1 = __half22float2(*reinterpret_cast<__half2*>(&v.y));
    a.x += f0.x; a.y += f0.y; a.z += f1.x; a.w += f1.y;
}

// ---------------------------------------------------------------------------
// K1: convert C tables 1..3 to fp16. Pure streaming; 8 floats per thread.
// ---------------------------------------------------------------------------
__global__ void __launch_bounds__(256) convert_kernel(const float* __restrict__ C)
{
    const size_t i = ((size_t)blockIdx.x * 256 + threadIdx.x) * 8;
    if (i >= CN) return;
    const float4* src = reinterpret_cast<const float4*>(C + (size_t)VOCAB * DIM + i);
    float4 a = src[0], b = src[1];
    union { __half2 h[4]; uint4 u; } cv;
    cv.h[0] = __floats2half2_rn(a.x, a.y);
    cv.h[1] = __floats2half2_rn(a.z, a.w);
    cv.h[2] = __floats2half2_rn(b.x, b.y);
    cv.h[3] = __floats2half2_rn(b.z, b.w);
    *reinterpret_cast<uint4*>(g_Ch + i) = cv.u;
}

// ---------------------------------------------------------------------------
// K2: gather-sum tables 1..3 (fp16 in, fp32 acc, fp16 out). Warp per (t,b,slot).
// Last table-1 block per batch computes u1[b] = mean slot memory (hop 0).
// ---------------------------------------------------------------------------
__global__ void __launch_bounds__(256) gather_kernel(
    const int* __restrict__ story, const int* __restrict__ kb)
{
    const int lane = threadIdx.x & 31;
    const int wg   = blockIdx.x * 8 + (threadIdx.x >> 5);
    const int t    = wg / (BATCH * SLOTS);           // 0..2 -> table t+1
    const int rem  = wg % (BATCH * SLOTS);
    const int b    = rem / SLOTS;
    const int slot = rem % SLOTS;

    const __half* __restrict__ Ct = g_Ch + (size_t)t * VOCAB * DIM;
    float4 acc = make_float4(0.f, 0.f, 0.f, 0.f);

    if (slot < M_SLOTS) {
        const int* toks = story + ((size_t)b * M_SLOTS + slot) * S_TOK;
        int tk[S_TOK];
        #pragma unroll
        for (int j = 0; j < S_TOK; ++j) tk[j] = toks[j];
        #pragma unroll
        for (int j = 0; j < S_TOK; ++j) {
            uint2 v = reinterpret_cast<const uint2*>(Ct + (size_t)tk[j] * DIM)[lane];
            acc_u2(acc, v);
        }
    } else {
        const int* toks = kb + ((size_t)b * T_TREE + (slot - M_SLOTS)) * L_TOK;
        float4 a0 = make_float4(0.f, 0.f, 0.f, 0.f);
        float4 a1 = a0, a2 = a0, a3 = a0;
        #pragma unroll 4
        for (int j = 0; j < L_TOK; j += 4) {
            int t0 = toks[j + 0], t1 = toks[j + 1];
            int t2 = toks[j + 2], t3 = toks[j + 3];
            uint2 v0 = reinterpret_cast<const uint2*>(Ct + (size_t)t0 * DIM)[lane];
            uint2 v1 = reinterpret_cast<const uint2*>(Ct + (size_t)t1 * DIM)[lane];
            uint2 v2 = reinterpret_cast<const uint2*>(Ct + (size_t)t2 * DIM)[lane];
            uint2 v3 = reinterpret_cast<const uint2*>(Ct + (size_t)t3 * DIM)[lane];
            acc_u2(a0, v0); acc_u2(a1, v1); acc_u2(a2, v2); acc_u2(a3, v3);
        }
        acc.x = (a0.x + a1.x) + (a2.x + a3.x);
        acc.y = (a0.y + a1.y) + (a2.y + a3.y);
        acc.z = (a0.z + a1.z) + (a2.z + a3.z);
        acc.w = (a0.w + a1.w) + (a2.w + a3.w);
    }

    union { __half2 h[2]; uint2 u; } st;
    st.h[0] = __floats2half2_rn(acc.x, acc.y);
    st.h[1] = __floats2half2_rn(acc.z, acc.w);
    reinterpret_cast<uint2*>(g_Mh + (size_t)wg * DIM)[lane] = st.u;

    // ---- last table-1 block for this batch computes u1[b] ----
    if (t == 0) {
        __threadfence();
        __syncthreads();
        __shared__ int s_old;
        if (threadIdx.x == 0)
            s_old = atomicAdd(&g_cnt[2 * BATCH + b], 1);
        __syncthreads();
        if (s_old == U1_BLOCKS - 1) {
            const int d2  = threadIdx.x & 63;    // half2 index (dims 2*d2, 2*d2+1)
            const int grp = threadIdx.x >> 6;    // 0..3, 160 slots each
            const __half2* __restrict__ base =
                reinterpret_cast<const __half2*>(g_Mh + (size_t)b * SLOTS * DIM);
            float2 a = make_float2(0.f, 0.f);
            #pragma unroll 8
            for (int s = grp * 160; s < (grp + 1) * 160; ++s) {
                float2 v = __half22float2(base[(size_t)s * 64 + d2]);
                a.x += v.x; a.y += v.y;
            }
            __shared__ float2 sm[256];
            sm[threadIdx.x] = a;
            __syncthreads();
            if (grp == 0) {
                float2 tot = sm[d2];
                #pragma unroll
                for (int i = 1; i < 4; ++i) {
                    float2 p = sm[i * 64 + d2];
                    tot.x += p.x; tot.y += p.y;
                }
                g_u[b * DIM + 2 * d2]     = tot.x * (1.0f / SLOTS);
                g_u[b * DIM + 2 * d2 + 1] = tot.y * (1.0f / SLOTS);
            }
            if (threadIdx.x == 0) g_cnt[2 * BATCH + b] = 0;   // reset for replay
        }
    }
}

// ---------------------------------------------------------------------------
// One hop: block = (b, split) handles 16 slots; last split-block combines
// all 40 flash partials into dst[b] = u_prev + o/s.
// ---------------------------------------------------------------------------
__global__ void __launch_bounds__(256) hop_kernel(int kidx, int vidx,
                                                  int uidx, int pidx,
                                                  float* __restrict__ dst)
{
    const int b     = blockIdx.x / SPLITS;
    const int split = blockIdx.x % SPLITS;
    const int tid   = threadIdx.x;
    const int w     = tid >> 5;
    const int lane  = tid & 31;

    __shared__ float  s_score[SLOTS_PB];
    __shared__ float4 s_part[8][32];
    __shared__ float  s_ms[2];

    const float4 u4 =
        reinterpret_cast<const float4*>(g_u + (uidx * BATCH + b) * DIM)[lane];

    const __half* __restrict__ Mk =
        g_Mh + ((size_t)(kidx * BATCH + b) * SLOTS + split * SLOTS_PB) * DIM;
    const __half* __restrict__ Mv =
        g_Mh + ((size_t)(vidx * BATCH + b) * SLOTS + split * SLOTS_PB) * DIM;

    // scores: warp w handles local slots w, w+8
    #pragma unroll
    for (int k = 0; k < SLOTS_PB / 8; ++k) {
        const int ls = w + k * 8;
        uint2 raw = reinterpret_cast<const uint2*>(Mk + (size_t)ls * DIM)[lane];
        float4 v = make_float4(0.f, 0.f, 0.f, 0.f);
        acc_u2(v, raw);
        float p = v.x * u4.x + v.y * u4.y + v.z * u4.z + v.w * u4.w;
        p = warp_sum(p);
        if (lane == 0) s_score[ls] = p;
    }
    __syncthreads();

    // local softmax over 16 scores
    if (w == 0) {
        float sc = (lane < SLOTS_PB) ? s_score[lane] : -1e30f;
        float m  = warp_max(sc);
        float e  = (lane < SLOTS_PB) ? __expf(sc - m) : 0.f;
        float s  = warp_sum(e);
        if (lane < SLOTS_PB) s_score[lane] = e;
        if (lane == 0) { s_ms[0] = m; s_ms[1] = s; }
    }
    __syncthreads();

    // weighted value partial
    float4 o4 = make_float4(0.f, 0.f, 0.f, 0.f);
    #pragma unroll
    for (int k = 0; k < SLOTS_PB / 8; ++k) {
        const int ls = w + k * 8;
        const float p = s_score[ls];
        uint2 raw = reinterpret_cast<const uint2*>(Mv + (size_t)ls * DIM)[lane];
        float4 v = make_float4(0.f, 0.f, 0.f, 0.f);
        acc_u2(v, raw);
        o4.x += p * v.x; o4.y += p * v.y; o4.z += p * v.z; o4.w += p * v.w;
    }
    s_part[w][lane] = o4;
    __syncthreads();

    if (w == 0) {
        float4 r = make_float4(0.f, 0.f, 0.f, 0.f);
        #pragma unroll
        for (int i = 0; i < 8; ++i) {
            float4 p = s_part[i][lane];
            r.x += p.x; r.y += p.y; r.z += p.z; r.w += p.w;
        }
        float* rec = g_part + ((size_t)(pidx * BATCH + b) * SPLITS + split) * REC;
        reinterpret_cast<float4*>(rec + 4)[lane] = r;
        if (lane == 0) { rec[0] = s_ms[0]; rec[1] = s_ms[1]; }
    }

    // ---- last-block combine ----
    __threadfence();
    __syncthreads();
    __shared__ int s_old;
    if (tid == 0)
        s_old = atomicAdd(&g_cnt[pidx * BATCH + b], 1);
    __syncthreads();
    if (s_old != SPLITS - 1) return;

    const float* __restrict__ base =
        g_part + ((size_t)(pidx * BATCH + b)) * SPLITS * REC;

    __shared__ float  c_m[8], c_s[8];
    __shared__ float4 c_o[8][32];

    float mi = (tid < SPLITS) ? __ldcg(base + (size_t)tid * REC) : -1e30f;
    mi = warp_max(mi);
    if (lane == 0) c_m[w] = mi;
    __syncthreads();
    float m = c_m[0];
    #pragma unroll
    for (int i = 1; i < 8; ++i) m = fmaxf(m, c_m[i]);

    // warp w accumulates records w, w+8, ..., w+32 (5 each)
    float  s_acc = 0.f;
    float4 o4c = make_float4(0.f, 0.f, 0.f, 0.f);
    #pragma unroll
    for (int k = 0; k < SPLITS / 8; ++k) {
        const float* rec = base + (size_t)(w + 8 * k) * REC;
        float e = __expf(__ldcg(rec) - m);
        s_acc += __ldcg(rec + 1) * e;
        float4 oi = __ldcg(reinterpret_cast<const float4*>(rec + 4) + lane);
        o4c.x += e * oi.x; o4c.y += e * oi.y; o4c.z += e * oi.z; o4c.w += e * oi.w;
    }
    c_o[w][lane] = o4c;
    if (lane == 0) c_s[w] = s_acc;
    __syncthreads();

    if (w == 0) {
        float stot = 0.f;
        #pragma unroll
        for (int i = 0; i < 8; ++i) stot += c_s[i];
        float4 r = make_float4(0.f, 0.f, 0.f, 0.f);
        #pragma unroll
        for (int i = 0; i < 8; ++i) {
            float4 p = c_o[i][lane];
            r.x += p.x; r.y += p.y; r.z += p.z; r.w += p.w;
        }
        const float inv = 1.0f / stot;
        float4 res;
        res.x = u4.x + r.x * inv;
        res.y = u4.y + r.y * inv;
        res.z = u4.z + r.z * inv;
        res.w = u4.w + r.w * inv;
        reinterpret_cast<float4*>(dst + b * DIM)[lane] = res;
    }
    if (tid == 0) g_cnt[pidx * BATCH + b] = 0;   // reset for graph replay
}

// ---------------------------------------------------------------------------
extern "C" void kernel_launch(void* const* d_in, const int* in_sizes, int n_in,
                              void* d_out, int out_size)
{
    const float* C     = (const float*)d_in[0];  // [4, 50257, 128]
    const int*   story = (const int*)  d_in[1];  // [32, 512, 6]
    const int*   kb    = (const int*)  d_in[2];  // [32, 128, 64]
    float*       out   = (float*)d_out;          // [32, 128]

    float* u2;
    cudaGetSymbolAddress((void**)&u2, g_u);
    u2 += BATCH * DIM;

    const int cthreads = (int)(CN / 8);                      // 2,412,336
    convert_kernel<<<(cthreads + 255) / 256, 256>>>(C);      // fp32 -> fp16
    gather_kernel<<<3 * GBLK_PER_TAB, 256>>>(story, kb);     // 7680, + u1
    hop_kernel<<<BATCH * SPLITS, 256>>>(0, 1, 0, 0, u2);     // hop1 -> u2
    hop_kernel<<<BATCH * SPLITS, 256>>>(1, 2, 1, 1, out);    // hop2 -> out
}